// round 16
// baseline (speedup 1.0000x reference)
#include <cuda_runtime.h>
#include <cuda_fp16.h>
#include <cstdint>

// Problem constants
#define MDIM 32
#define KDIM 8192
#define NDIM 28672
#define N_TILE 128                // n-columns per CTA (4 warps x 32)
#define THREADS 128
#define KSPLIT 16
#define K_PER_SPLIT (KDIM / KSPLIT)       // 512
#define S_K 16                            // weight k-rows per pipeline stage
#define NBUF 4                            // per-warp cp.async ring depth
#define TOTAL_STAGES (K_PER_SPLIT / S_K)  // 32
#define K_CHUNK 256                       // act chunk (16 stages) -> 1 swap
#define APAD 8
#define WPITCH 36                         // int32 words per k-row in warp tile (32+4)
#define STAGE_WORDS (S_K * WPITCH)        // 576 words = 2304 B
#define NBLOCKS (NDIM / N_TILE)           // 224

#define SA_BYTES (MDIM * (K_CHUNK + APAD) * 2)   // 16896
#define SW_BYTES (4 * NBUF * STAGE_WORDS * 4)    // 36864
#define SMEM_BYTES (SA_BYTES + SW_BYTES)         // 53760 -> 4 CTAs/SM

// Split-K accumulator (fp32, unscaled): 3.67 MB, L2-resident.
// Zero-initialized at load; finishing CTA re-zeros its slab each launch.
__device__ float g_accum[MDIM * NDIM];
__device__ int   g_counter[NBLOCKS];      // zero-init; self-resetting

// ---------------------------------------------------------------------------
__device__ __forceinline__ void mma16816(float c[4], const uint32_t a[4],
                                         uint32_t b0, uint32_t b1) {
    asm volatile(
        "mma.sync.aligned.m16n8k16.row.col.f32.f16.f16.f32 "
        "{%0,%1,%2,%3}, {%4,%5,%6,%7}, {%8,%9}, {%0,%1,%2,%3};"
        : "+f"(c[0]), "+f"(c[1]), "+f"(c[2]), "+f"(c[3])
        : "r"(a[0]), "r"(a[1]), "r"(a[2]), "r"(a[3]), "r"(b0), "r"(b1));
}

__device__ __forceinline__ void ldsm_x4(uint32_t a[4], uint32_t smem_addr) {
    asm volatile(
        "ldmatrix.sync.aligned.m8n8.x4.shared.b16 {%0,%1,%2,%3}, [%4];"
        : "=r"(a[0]), "=r"(a[1]), "=r"(a[2]), "=r"(a[3])
        : "r"(smem_addr));
}

// Two int32 weights (in [-127,127]) -> packed half2 {w0, w1}. Exact.
__device__ __forceinline__ uint32_t cvt_w2(int w0, int w1) {
    uint32_t t, h;
    asm("prmt.b32 %0, %1, %2, 0x0400;" : "=r"(t) : "r"(w0), "r"(w1));
    asm("lop3.b32 %0, %1, %2, %3, 0x6A;"            // (a & b) ^ c
        : "=r"(h) : "r"(t), "n"(0x00FF00FF), "n"(0x64806480));
    const uint32_t bias = 0x64806480u;               // half2(1152, 1152)
    __half2 hv = __hsub2(*reinterpret_cast<__half2*>(&h),
                         *reinterpret_cast<const __half2*>(&bias));
    return *reinterpret_cast<uint32_t*>(&hv);
}

__device__ __forceinline__ void cp_async16(uint32_t smem_dst, const void* gsrc) {
    asm volatile("cp.async.cg.shared.global [%0], [%1], 16;\n"
                 :: "r"(smem_dst), "l"(gsrc));
}
__device__ __forceinline__ void cp_commit() {
    asm volatile("cp.async.commit_group;");
}
__device__ __forceinline__ void cp_wait3() {
    asm volatile("cp.async.wait_group 3;");
}
__device__ __forceinline__ void red_add_f32(float* addr, float v) {
    asm volatile("red.global.add.f32 [%0], %1;" :: "l"(addr), "f"(v) : "memory");
}

// ---------------------------------------------------------------------------
__global__ void __launch_bounds__(THREADS)
dq_gemm_kernel(const float* __restrict__ act,     // f32 (fp16 values)
               const int*   __restrict__ weight,  // int32 (int8 values)
               const float* __restrict__ scale,
               float*       __restrict__ out)
{
    extern __shared__ char smem[];
    __half* sA = reinterpret_cast<__half*>(smem);               // [32][264] fp16
    int*    sWall = reinterpret_cast<int*>(smem + SA_BYTES);    // [4][NBUF][576]
    __shared__ int sFlag;

    const int tid  = threadIdx.x;
    const int warp = tid >> 5;
    const int lane = tid & 31;
    const int gid  = lane >> 2;   // 0..7
    const int tig  = lane & 3;    // 0..3

    const int nblk  = blockIdx.x * N_TILE;
    const int kz    = blockIdx.y;
    const int kbase = kz * K_PER_SPLIT;

    float acc[2][4][4];
#pragma unroll
    for (int i = 0; i < 2; i++)
#pragma unroll
        for (int j = 0; j < 4; j++)
#pragma unroll
            for (int c = 0; c < 4; c++) acc[i][j][c] = 0.0f;

    // A-side ldmatrix addresses
    const int lrow = lane & 15;
    const int lcol = (lane >> 4) * 8;
    const uint32_t sA_base = (uint32_t)__cvta_generic_to_shared(sA);
    const uint32_t rowbytesA = (K_CHUNK + APAD) * 2;
    const uint32_t addrA0 = sA_base + lrow * rowbytesA + lcol * 2;         // m 0-15
    const uint32_t addrA1 = sA_base + (16 + lrow) * rowbytesA + lcol * 2;  // m 16-31

    // Per-warp weight cp.async: warp owns cols [warp*32, warp*32+32) (128B lines).
    const int crow = lane >> 3;         // 0..3
    const int ccol = (lane & 7) * 4;    // 0,4,...,28
    const int* wsrc = weight + (size_t)crow * NDIM + nblk + warp * 32 + ccol;
    int* sWw = sWall + warp * (NBUF * STAGE_WORDS);
    const uint32_t sWw_base = (uint32_t)__cvta_generic_to_shared(sWw);
    const uint32_t cp_dst0 = sWw_base + (uint32_t)((crow * WPITCH + ccol) * 4);

    // B-fragment LDS base word offset (conflict-free by pitch 36)
    const int boff = 2 * tig * WPITCH + gid;

    auto cp_stage = [&](int st) {
        const int* src = wsrc + (size_t)(kbase + st * S_K) * NDIM;
        const uint32_t dst = cp_dst0 + (uint32_t)((st % NBUF) * STAGE_WORDS * 4);
#pragma unroll
        for (int j = 0; j < 4; j++)
            cp_async16(dst + j * (4 * WPITCH * 4), src + (size_t)(4 * j) * NDIM);
    };
    auto load_act = [&](int kc) {
#pragma unroll
        for (int i = tid; i < MDIM * (K_CHUNK / 4); i += THREADS) {
            const int r = i >> 6;           // K_CHUNK/4 == 64
            const int c = i & 63;
            const float4 v = *reinterpret_cast<const float4*>(
                act + (size_t)r * KDIM + kc + c * 4);
            __half2* dst = reinterpret_cast<__half2*>(&sA[r * (K_CHUNK + APAD) + c * 4]);
            dst[0] = __floats2half2_rn(v.x, v.y);
            dst[1] = __floats2half2_rn(v.z, v.w);
        }
    };
    auto compute_stage = [&](int buf, int choff) {
        const int* wb = sWw + buf * STAGE_WORDS;
        uint32_t afrag0[4], afrag1[4];
        ldsm_x4(afrag0, addrA0 + choff * 2);
        ldsm_x4(afrag1, addrA1 + choff * 2);
#pragma unroll
        for (int nt = 0; nt < 4; nt++) {
            const int* p = wb + boff + nt * 8;
            const int w0 = p[0];
            const int w1 = p[WPITCH];
            const int w2 = p[8 * WPITCH];
            const int w3 = p[9 * WPITCH];
            const uint32_t b0 = cvt_w2(w0, w1);
            const uint32_t b1 = cvt_w2(w2, w3);
            mma16816(acc[0][nt], afrag0, b0, b1);
            mma16816(acc[1][nt], afrag1, b0, b1);
        }
    };

    // --- prologue: 3 per-warp weight stages in flight + act chunk 0
    cp_stage(0); cp_commit();
    cp_stage(1); cp_commit();
    cp_stage(2); cp_commit();
    load_act(kbase);
    __syncthreads();

#pragma unroll 1
    for (int st = 0; st < TOTAL_STAGES; st++) {
        if (st + 3 < TOTAL_STAGES) cp_stage(st + 3);    // prefetch FIRST
        cp_commit();                                    // (empty at tail)
        if (st == 16) {                                 // single act chunk swap
            __syncthreads();
            load_act(kbase + st * S_K);
            __syncthreads();
        }
        cp_wait3();                                     // stage st resident
        compute_stage(st & (NBUF - 1), (st & 15) * S_K);
    }

    // --- epilogue: atomically accumulate into L2-resident g_accum
#pragma unroll
    for (int mt = 0; mt < 2; mt++) {
#pragma unroll
        for (int nt = 0; nt < 4; nt++) {
            const int col = nblk + warp * 32 + nt * 8 + 2 * tig;
            const int r0 = mt * 16 + gid;
#pragma unroll
            for (int hr = 0; hr < 2; hr++) {
                const int r = r0 + hr * 8;
                float* p = g_accum + (size_t)r * NDIM + col;
                red_add_f32(p,     acc[mt][nt][hr * 2 + 0]);
                red_add_f32(p + 1, acc[mt][nt][hr * 2 + 1]);
            }
        }
    }

    // --- fused finish: last CTA of this n-block scales/rounds/stores its slab
    __syncthreads();
    if (tid == 0) {
        __threadfence();                      // release the red.adds
        const int old = atomicAdd(&g_counter[blockIdx.x], 1);
        sFlag = (old == KSPLIT - 1);
    }
    __syncthreads();
    if (sFlag) {
        __threadfence();                      // acquire all CTAs' red.adds
#pragma unroll
        for (int i = 0; i < 8; i++) {
            const int lin = i * THREADS + tid;        // 0..1023 float4s
            const int row = lin >> 5;                 // 32 float4 per row
            const int c4  = lin & 31;
            const int col = nblk + c4 * 4;
            const size_t addr = (size_t)row * NDIM + col;

            float4 s = *reinterpret_cast<const float4*>(&g_accum[addr]);
            const float4 sc = *reinterpret_cast<const float4*>(scale + col);
            float4 o;
            o.x = __half2float(__float2half_rn(s.x * sc.x));
            o.y = __half2float(__float2half_rn(s.y * sc.y));
            o.z = __half2float(__float2half_rn(s.z * sc.z));
            o.w = __half2float(__float2half_rn(s.w * sc.w));
            *reinterpret_cast<float4*>(out + addr) = o;
            // re-zero for next graph replay
            *reinterpret_cast<float4*>(&g_accum[addr]) =
                make_float4(0.f, 0.f, 0.f, 0.f);
        }
        if (tid == 0) g_counter[blockIdx.x] = 0;   // reset counter
    }
}

// ---------------------------------------------------------------------------
extern "C" void kernel_launch(void* const* d_in, const int* in_sizes, int n_in,
                              void* d_out, int out_size) {
    const float* act    = (const float*)d_in[0];   // [32, 8192] f32
    const int*   weight = (const int*)d_in[1];     // [8192, 28672] int32
    const float* scale  = (const float*)d_in[2];   // [28672] f32
    float*       out    = (float*)d_out;           // [32, 28672] f32

    cudaFuncSetAttribute(dq_gemm_kernel,
                         cudaFuncAttributeMaxDynamicSharedMemorySize, SMEM_BYTES);

    dim3 grid(NBLOCKS, KSPLIT);
    dq_gemm_kernel<<<grid, THREADS, SMEM_BYTES>>>(act, weight, scale, out);
}

// round 17
// speedup vs baseline: 1.0548x; 1.0548x over previous
#include <cuda_runtime.h>
#include <cuda_fp16.h>
#include <cstdint>

// Problem constants
#define MDIM 32
#define KDIM 8192
#define NDIM 28672
#define N_TILE 128                // n-columns per CTA (4 warps x 32)
#define THREADS 128
#define KSPLIT 8
#define K_PER_SPLIT (KDIM / KSPLIT)       // 1024
#define S_K 16                            // weight k-rows per pipeline stage
#define NBUF 3                            // per-warp cp.async ring depth
#define TOTAL_STAGES (K_PER_SPLIT / S_K)  // 64
#define K_CHUNK 256                       // act chunk (16 stages)
#define APAD 8
#define WPITCH 36                         // int32 words per k-row in warp tile (32+4)
#define STAGE_WORDS (S_K * WPITCH)        // 576 words = 2304 B
#define NBLOCKS (NDIM / N_TILE)           // 224

// Split-K accumulator (fp32, unscaled): 3.67 MB -> L2-resident.
// Zero-initialized at module load; finishing CTA re-zeros its slab per launch.
__device__ float g_accum[MDIM * NDIM];
__device__ int   g_counter[NBLOCKS];      // zero-init; self-resetting

// ---------------------------------------------------------------------------
__device__ __forceinline__ void mma16816(float c[4], const uint32_t a[4],
                                         uint32_t b0, uint32_t b1) {
    asm volatile(
        "mma.sync.aligned.m16n8k16.row.col.f32.f16.f16.f32 "
        "{%0,%1,%2,%3}, {%4,%5,%6,%7}, {%8,%9}, {%0,%1,%2,%3};"
        : "+f"(c[0]), "+f"(c[1]), "+f"(c[2]), "+f"(c[3])
        : "r"(a[0]), "r"(a[1]), "r"(a[2]), "r"(a[3]), "r"(b0), "r"(b1));
}

__device__ __forceinline__ void ldsm_x4(uint32_t a[4], uint32_t smem_addr) {
    asm volatile(
        "ldmatrix.sync.aligned.m8n8.x4.shared.b16 {%0,%1,%2,%3}, [%4];"
        : "=r"(a[0]), "=r"(a[1]), "=r"(a[2]), "=r"(a[3])
        : "r"(smem_addr));
}

// Two int32 weights (in [-127,127]) -> packed half2 {w0, w1}. Exact.
__device__ __forceinline__ uint32_t cvt_w2(int w0, int w1) {
    uint32_t t, h;
    asm("prmt.b32 %0, %1, %2, 0x0400;" : "=r"(t) : "r"(w0), "r"(w1));
    asm("lop3.b32 %0, %1, %2, %3, 0x6A;"            // (a & b) ^ c
        : "=r"(h) : "r"(t), "n"(0x00FF00FF), "n"(0x64806480));
    const uint32_t bias = 0x64806480u;               // half2(1152, 1152)
    __half2 hv = __hsub2(*reinterpret_cast<__half2*>(&h),
                         *reinterpret_cast<const __half2*>(&bias));
    return *reinterpret_cast<uint32_t*>(&hv);
}

__device__ __forceinline__ void cp_async16(uint32_t smem_dst, const void* gsrc) {
    asm volatile("cp.async.cg.shared.global [%0], [%1], 16;\n"
                 :: "r"(smem_dst), "l"(gsrc));
}
__device__ __forceinline__ void cp_commit() {
    asm volatile("cp.async.commit_group;");
}
__device__ __forceinline__ void cp_wait2() {
    asm volatile("cp.async.wait_group 2;");
}
__device__ __forceinline__ void red_add_f32(float* addr, float v) {
    asm volatile("red.global.add.f32 [%0], %1;" :: "l"(addr), "f"(v) : "memory");
}

// ---------------------------------------------------------------------------
__global__ void __launch_bounds__(THREADS)
dq_gemm_kernel(const float* __restrict__ act,     // f32 (fp16 values)
               const int*   __restrict__ weight,  // int32 (int8 values)
               const float* __restrict__ scale,
               float*       __restrict__ out)
{
    __shared__ __half sA[MDIM][K_CHUNK + APAD];              // 16.9 KB
    __shared__ int    sW[4][NBUF][STAGE_WORDS];              // 27.6 KB
    __shared__ int    sFlag;

    const int tid  = threadIdx.x;
    const int warp = tid >> 5;
    const int lane = tid & 31;
    const int gid  = lane >> 2;   // 0..7
    const int tig  = lane & 3;    // 0..3

    const int nblk  = blockIdx.x * N_TILE;
    const int kz    = blockIdx.y;
    const int kbase = kz * K_PER_SPLIT;

    float acc[2][4][4];
#pragma unroll
    for (int i = 0; i < 2; i++)
#pragma unroll
        for (int j = 0; j < 4; j++)
#pragma unroll
            for (int c = 0; c < 4; c++) acc[i][j][c] = 0.0f;

    // A-side ldmatrix addresses
    const int lrow = lane & 15;
    const int lcol = (lane >> 4) * 8;
    const uint32_t sA_base = (uint32_t)__cvta_generic_to_shared(&sA[0][0]);
    const uint32_t rowbytesA = (K_CHUNK + APAD) * 2;
    const uint32_t addrA0 = sA_base + lrow * rowbytesA + lcol * 2;         // m 0-15
    const uint32_t addrA1 = sA_base + (16 + lrow) * rowbytesA + lcol * 2;  // m 16-31

    // Per-warp weight cp.async: warp owns cols [warp*32, warp*32+32) (128B lines).
    const int crow = lane >> 3;         // 0..3
    const int ccol = (lane & 7) * 4;    // 0,4,...,28
    const int* wsrc = weight + (size_t)crow * NDIM + nblk + warp * 32 + ccol;
    const uint32_t sWw_base = (uint32_t)__cvta_generic_to_shared(&sW[warp][0][0]);
    const uint32_t cp_dst0 = sWw_base + (uint32_t)((crow * WPITCH + ccol) * 4);
    const int* wbase = &sW[warp][0][0];

    // B-fragment LDS base word offset (conflict-free by pitch 36)
    const int boff = 2 * tig * WPITCH + gid;

    auto cp_stage = [&](int st) {
        const int* src = wsrc + (size_t)(kbase + st * S_K) * NDIM;
        const uint32_t dst = cp_dst0 + (uint32_t)((st % NBUF) * STAGE_WORDS * 4);
#pragma unroll
        for (int j = 0; j < 4; j++)
            cp_async16(dst + j * (4 * WPITCH * 4), src + (size_t)(4 * j) * NDIM);
    };
    auto load_act = [&](int kc) {
#pragma unroll
        for (int i = tid; i < MDIM * (K_CHUNK / 4); i += THREADS) {
            const int r = i >> 6;           // K_CHUNK/4 == 64
            const int c = i & 63;
            const float4 v = *reinterpret_cast<const float4*>(
                act + (size_t)r * KDIM + kc + c * 4);
            __half2* dst = reinterpret_cast<__half2*>(&sA[r][c * 4]);
            dst[0] = __floats2half2_rn(v.x, v.y);
            dst[1] = __floats2half2_rn(v.z, v.w);
        }
    };
    auto compute_stage = [&](int buf, int choff) {
        const int* wb = wbase + buf * STAGE_WORDS;
        uint32_t afrag0[4], afrag1[4];
        ldsm_x4(afrag0, addrA0 + choff * 2);
        ldsm_x4(afrag1, addrA1 + choff * 2);
#pragma unroll
        for (int nt = 0; nt < 4; nt++) {
            const int* p = wb + boff + nt * 8;
            const int w0 = p[0];
            const int w1 = p[WPITCH];
            const int w2 = p[8 * WPITCH];
            const int w3 = p[9 * WPITCH];
            const uint32_t b0 = cvt_w2(w0, w1);
            const uint32_t b1 = cvt_w2(w2, w3);
            mma16816(acc[0][nt], afrag0, b0, b1);
            mma16816(acc[1][nt], afrag1, b0, b1);
        }
    };

    // --- prologue: 2 per-warp weight stages in flight + act chunk 0
    cp_stage(0); cp_commit();
    cp_stage(1); cp_commit();
    load_act(kbase);
    __syncthreads();

#pragma unroll 1
    for (int st = 0; st < TOTAL_STAGES; st++) {
        if (st + 2 < TOTAL_STAGES) cp_stage(st + 2);    // weight prefetch FIRST
        cp_commit();                                    // (empty at tail)
        if ((st & 15) == 0 && st > 0) {                 // act chunk swap (x3)
            __syncthreads();
            load_act(kbase + st * S_K);
            __syncthreads();
        }
        cp_wait2();                                     // stage st resident
        compute_stage(st % NBUF, (st & 15) * S_K);
    }

    // --- epilogue: atomically accumulate into L2-resident g_accum
#pragma unroll
    for (int mt = 0; mt < 2; mt++) {
#pragma unroll
        for (int nt = 0; nt < 4; nt++) {
            const int col = nblk + warp * 32 + nt * 8 + 2 * tig;
            const int r0 = mt * 16 + gid;
#pragma unroll
            for (int hr = 0; hr < 2; hr++) {
                const int r = r0 + hr * 8;
                float* p = g_accum + (size_t)r * NDIM + col;
                red_add_f32(p,     acc[mt][nt][hr * 2 + 0]);
                red_add_f32(p + 1, acc[mt][nt][hr * 2 + 1]);
            }
        }
    }

    // --- fused finish: last CTA of this n-block scales/rounds/stores its slab
    __syncthreads();
    if (tid == 0) {
        __threadfence();                      // release the red.adds
        const int old = atomicAdd(&g_counter[blockIdx.x], 1);
        sFlag = (old == KSPLIT - 1);
    }
    __syncthreads();
    if (sFlag) {
        __threadfence();                      // acquire all CTAs' red.adds
#pragma unroll
        for (int i = 0; i < 8; i++) {
            const int lin = i * THREADS + tid;        // 0..1023 float4s
            const int row = lin >> 5;                 // 32 float4 per row
            const int c4  = lin & 31;
            const int col = nblk + c4 * 4;
            const size_t addr = (size_t)row * NDIM + col;

            float4 s = *reinterpret_cast<const float4*>(&g_accum[addr]);
            const float4 sc = *reinterpret_cast<const float4*>(scale + col);
            float4 o;
            o.x = __half2float(__float2half_rn(s.x * sc.x));
            o.y = __half2float(__float2half_rn(s.y * sc.y));
            o.z = __half2float(__float2half_rn(s.z * sc.z));
            o.w = __half2float(__float2half_rn(s.w * sc.w));
            *reinterpret_cast<float4*>(out + addr) = o;
            // re-zero for next graph replay
            *reinterpret_cast<float4*>(&g_accum[addr]) =
                make_float4(0.f, 0.f, 0.f, 0.f);
        }
        if (tid == 0) g_counter[blockIdx.x] = 0;   // reset counter
    }
}

// ---------------------------------------------------------------------------
extern "C" void kernel_launch(void* const* d_in, const int* in_sizes, int n_in,
                              void* d_out, int out_size) {
    const float* act    = (const float*)d_in[0];   // [32, 8192] f32
    const int*   weight = (const int*)d_in[1];     // [8192, 28672] int32
    const float* scale  = (const float*)d_in[2];   // [28672] f32
    float*       out    = (float*)d_out;           // [32, 28672] f32

    dim3 grid(NBLOCKS, KSPLIT);
    dq_gemm_kernel<<<grid, THREADS>>>(act, weight, scale, out);
}